// round 1
// baseline (speedup 1.0000x reference)
#include <cuda_runtime.h>
#include <stdint.h>

#define D 256
#define BQ 1024
#define KTOP 1024
#define MMAX 100000
#define CAND_MAX 4096
#define FEAT_BLOCKS 128

// ---------------- static device scratch (no allocations allowed) ----------------
__device__ float g_pfsum[FEAT_BLOCKS][D];
__device__ float g_pfsq[FEAT_BLOCKS];
__device__ float g_fsum[D];
__device__ float g_fsq;
__device__ unsigned long long g_keys[MMAX];
__device__ int g_hist1[4096];
__device__ int g_hist2[65536];
__device__ int g_T1, g_C1, g_T2;
__device__ unsigned long long g_cand[CAND_MAX];
__device__ int g_ncand;
__device__ int g_topidx[KTOP];

// ---------------- K0: zero histograms + counters ----------------
__global__ void k_zero() {
    int i = blockIdx.x * blockDim.x + threadIdx.x;
    int stride = gridDim.x * blockDim.x;
    for (; i < 4096 + 65536; i += stride) {
        if (i < 4096) g_hist1[i] = 0;
        else          g_hist2[i - 4096] = 0;
    }
    if (blockIdx.x == 0 && threadIdx.x == 0) g_ncand = 0;
}

// ---------------- K1: per-block partial feature sums (deterministic) ----------------
__global__ void k_feat1(const float* __restrict__ f) {
    const int RPB = BQ / FEAT_BLOCKS;  // 8 rows per block
    int blk = blockIdx.x;
    int d = threadIdx.x;               // 256 threads, one per feature dim
    float s = 0.f, sq = 0.f;
    int base = blk * RPB * D + d;
#pragma unroll
    for (int r = 0; r < RPB; r++) {
        float v = f[base + r * D];
        s += v;
        sq += v * v;
    }
    g_pfsum[blk][d] = s;
    __shared__ float red[256];
    red[d] = sq;
    __syncthreads();
    for (int st = 128; st > 0; st >>= 1) {
        if (d < st) red[d] += red[d + st];
        __syncthreads();
    }
    if (d == 0) g_pfsq[blk] = red[0];
}

// ---------------- K1b: final feature reduction ----------------
__global__ void k_feat2() {
    int d = threadIdx.x;  // 256
    float s = 0.f;
    for (int b = 0; b < FEAT_BLOCKS; b++) s += g_pfsum[b][d];
    g_fsum[d] = s;
    __shared__ float red[256];
    red[d] = (d < FEAT_BLOCKS) ? g_pfsq[d] : 0.f;
    __syncthreads();
    for (int st = 128; st > 0; st >>= 1) {
        if (d < st) red[d] += red[d + st];
        __syncthreads();
    }
    if (d == 0) g_fsq = red[0];
}

// ---------------- K2: scores + sortable keys + coarse histogram ----------------
// warp per row: 32 lanes x 8 floats (2x float4) each
__global__ void k_scores(const float* __restrict__ mem, int M) {
    __shared__ __align__(16) float sf[D];
    int tid = threadIdx.x;
    if (tid < D) sf[tid] = g_fsum[tid];
    __syncthreads();

    int warp = tid >> 5, lane = tid & 31;
    int row = blockIdx.x * 8 + warp;
    if (row >= M) return;

    const float4* m4 = (const float4*)(mem + (size_t)row * D);
    const float4* f4 = (const float4*)sf;
    float4 a = m4[lane * 2], b = m4[lane * 2 + 1];
    float4 fa = f4[lane * 2], fb = f4[lane * 2 + 1];

    const float Bf = (float)BQ;
    float acc = a.x * (Bf * a.x - 2.f * fa.x)
              + a.y * (Bf * a.y - 2.f * fa.y)
              + a.z * (Bf * a.z - 2.f * fa.z)
              + a.w * (Bf * a.w - 2.f * fa.w)
              + b.x * (Bf * b.x - 2.f * fb.x)
              + b.y * (Bf * b.y - 2.f * fb.y)
              + b.z * (Bf * b.z - 2.f * fb.z)
              + b.w * (Bf * b.w - 2.f * fb.w);
#pragma unroll
    for (int o = 16; o > 0; o >>= 1)
        acc += __shfl_down_sync(0xffffffffu, acc, o);

    if (lane == 0) {
        float score = -(acc + g_fsq);
        unsigned u = __float_as_uint(score);
        u = (u & 0x80000000u) ? ~u : (u | 0x80000000u);  // monotone: bigger u == bigger score
        unsigned long long key =
            ((unsigned long long)u << 32) | (unsigned)(~row);  // tie-break: smaller row wins
        g_keys[row] = key;
        atomicAdd(&g_hist1[u >> 20], 1);
    }
}

// ---------------- K3: coarse threshold (12-bit) ----------------
__global__ void k_thresh1() {
    __shared__ int csum[1024];
    __shared__ int ssum[32];
    int tid = threadIdx.x;  // 1024
    int s = 0;
    for (int b = tid * 4; b < tid * 4 + 4; b++) s += g_hist1[b];
    csum[tid] = s;
    __syncthreads();
    if (tid < 32) {
        int v = 0;
        for (int c = tid * 32; c < tid * 32 + 32; c++) v += csum[c];
        ssum[tid] = v;
    }
    __syncthreads();
    if (tid == 0) {
        int cum = 0, sc;
        for (sc = 31; sc >= 0; sc--) {
            if (cum + ssum[sc] >= KTOP) break;
            cum += ssum[sc];
        }
        int cc;
        for (cc = sc * 32 + 31; cc >= sc * 32; cc--) {
            if (cum + csum[cc] >= KTOP) break;
            cum += csum[cc];
        }
        int b;
        for (b = cc * 4 + 3; b >= cc * 4; b--) {
            if (cum + g_hist1[b] >= KTOP) break;
            cum += g_hist1[b];
        }
        g_T1 = b;   // threshold coarse bucket
        g_C1 = cum; // count strictly above it (< KTOP)
    }
}

// ---------------- K4: fine histogram (next 16 bits) over threshold bucket ----------------
__global__ void k_hist2k(int M) {
    int i = blockIdx.x * blockDim.x + threadIdx.x;
    if (i >= M) return;
    unsigned hi = (unsigned)(g_keys[i] >> 32);
    if ((int)(hi >> 20) == g_T1)
        atomicAdd(&g_hist2[(hi >> 4) & 0xFFFFu], 1);
}

// ---------------- K5: fine threshold ----------------
__global__ void k_thresh2() {
    __shared__ int csum[1024];
    __shared__ int ssum[32];
    int tid = threadIdx.x;  // 1024
    int s = 0;
    for (int b = tid * 64; b < tid * 64 + 64; b++) s += g_hist2[b];
    csum[tid] = s;
    __syncthreads();
    if (tid < 32) {
        int v = 0;
        for (int c = tid * 32; c < tid * 32 + 32; c++) v += csum[c];
        ssum[tid] = v;
    }
    __syncthreads();
    if (tid == 0) {
        int need = KTOP - g_C1;  // >= 1 by construction
        int cum = 0, sc;
        for (sc = 31; sc >= 0; sc--) {
            if (cum + ssum[sc] >= need) break;
            cum += ssum[sc];
        }
        int cc;
        for (cc = sc * 32 + 31; cc >= sc * 32; cc--) {
            if (cum + csum[cc] >= need) break;
            cum += csum[cc];
        }
        int b;
        for (b = cc * 64 + 63; b >= cc * 64; b--) {
            if (cum + g_hist2[b] >= need) break;
            cum += g_hist2[b];
        }
        g_T2 = b;
    }
}

// ---------------- K6: collect candidates ----------------
__global__ void k_collect(int M) {
    int i = blockIdx.x * blockDim.x + threadIdx.x;
    if (i >= M) return;
    unsigned long long key = g_keys[i];
    unsigned hi = (unsigned)(key >> 32);
    int b1 = hi >> 20;
    int T1 = g_T1;
    bool take = (b1 > T1) ||
                (b1 == T1 && (int)((hi >> 4) & 0xFFFFu) >= g_T2);
    if (take) {
        int p = atomicAdd(&g_ncand, 1);
        if (p < CAND_MAX) g_cand[p] = key;
    }
}

// ---------------- K7: bitonic sort candidates, emit ranked indices ----------------
__global__ void k_sort() {
    __shared__ unsigned long long s[CAND_MAX];  // 32 KB
    int tid = threadIdx.x;  // 1024
    int n = g_ncand;
    if (n > CAND_MAX) n = CAND_MAX;
    for (int i = tid; i < CAND_MAX; i += 1024)
        s[i] = (i < n) ? ~g_cand[i] : ~0ULL;  // sort ascending on ~key; pads go last
    __syncthreads();
    for (int k = 2; k <= CAND_MAX; k <<= 1) {
        for (int j = k >> 1; j > 0; j >>= 1) {
            for (int i = tid; i < CAND_MAX; i += 1024) {
                int ixj = i ^ j;
                if (ixj > i) {
                    unsigned long long va = s[i], vb = s[ixj];
                    bool up = ((i & k) == 0);
                    if ((va > vb) == up) { s[i] = vb; s[ixj] = va; }
                }
            }
            __syncthreads();
        }
    }
    for (int r = tid; r < KTOP; r += 1024) {
        unsigned long long key = ~s[r];          // r-th largest original key
        g_topidx[r] = (int)(~(unsigned)key);     // low 32 bits were ~row
    }
}

// ---------------- K8: gather winning rows ----------------
__global__ void k_gather(const float* __restrict__ mem, float* __restrict__ out) {
    int r = blockIdx.x;     // KTOP blocks
    int t = threadIdx.x;    // 64 threads, float4 each
    int idx = g_topidx[r];
    const float4* src = (const float4*)(mem + (size_t)idx * D);
    float4* dst = (float4*)(out + (size_t)r * D);
    dst[t] = src[t];
}

extern "C" void kernel_launch(void* const* d_in, const int* in_sizes, int n_in,
                              void* d_out, int out_size) {
    const float* p0 = (const float*)d_in[0];
    const float* p1 = (const float*)d_in[1];
    const float* feat;
    const float* mem;
    int M;
    if (in_sizes[0] <= in_sizes[1]) { feat = p0; mem = p1; M = in_sizes[1] / D; }
    else                            { feat = p1; mem = p0; M = in_sizes[0] / D; }

    k_zero<<<64, 256>>>();
    k_feat1<<<FEAT_BLOCKS, 256>>>(feat);
    k_feat2<<<1, 256>>>();
    k_scores<<<(M + 7) / 8, 256>>>(mem, M);
    k_thresh1<<<1, 1024>>>();
    k_hist2k<<<(M + 255) / 256, 256>>>(M);
    k_thresh2<<<1, 1024>>>();
    k_collect<<<(M + 255) / 256, 256>>>(M);
    k_sort<<<1, 1024>>>();
    k_gather<<<KTOP, 64>>>(mem, (float*)d_out);
}

// round 2
// speedup vs baseline: 1.8676x; 1.8676x over previous
#include <cuda_runtime.h>
#include <stdint.h>

#define D 256
#define BQ 1024
#define KTOP 1024
#define MMAX 100000
#define CAND_MAX 4096
#define FEAT_BLOCKS 128
#define NBINS (1 << 20)   // 20-bit single-level radix select
#define NCHUNK 1024

// ---------------- static device scratch ----------------
__device__ float g_pfsum[FEAT_BLOCKS][D];
__device__ float g_fsum[D];
__device__ unsigned long long g_keys[MMAX];
__device__ int g_hist[NBINS];          // 4 MB
__device__ int g_chunk[NCHUNK];
__device__ int g_Tbin;                 // threshold bin (bin >= T are candidates)
__device__ unsigned long long g_cand[CAND_MAX];
__device__ int g_ncand;
__device__ int g_topidx[KTOP];

// ---------------- K0: zero histogram + counters ----------------
__global__ void k_zero() {
    int i = blockIdx.x * blockDim.x + threadIdx.x;
    g_hist[i] = 0;
    if (i == 0) g_ncand = 0;
}

// ---------------- K1: per-block partial feature sums (deterministic) ----------------
__global__ void k_feat1(const float* __restrict__ f) {
    const int RPB = BQ / FEAT_BLOCKS;  // 8 rows per block
    int blk = blockIdx.x;
    int d = threadIdx.x;               // 256 threads, one per feature dim
    float s = 0.f;
    int base = blk * RPB * D + d;
#pragma unroll
    for (int r = 0; r < RPB; r++) s += f[base + r * D];
    g_pfsum[blk][d] = s;
}

// ---------------- K1b: final feature reduction ----------------
__global__ void k_feat2() {
    int d = threadIdx.x;  // 256
    float s = 0.f;
#pragma unroll 8
    for (int b = 0; b < FEAT_BLOCKS; b++) s += g_pfsum[b][d];
    g_fsum[d] = s;
}

// ---------------- K2: scores + sortable keys + 20-bit histogram ----------------
// Warp processes 4 rows; 8 independent float4 loads in flight per thread (MLP=8).
__global__ void k_scores(const float* __restrict__ mem, int M) {
    __shared__ __align__(16) float sf[D];
    int tid = threadIdx.x;
    sf[tid] = g_fsum[tid];
    __syncthreads();

    int warp = tid >> 5, lane = tid & 31;
    int base_row = (blockIdx.x * 8 + warp) * 4;
    if (base_row >= M) return;

    const float4* f4 = (const float4*)sf;
    float4 fa = f4[lane * 2], fb = f4[lane * 2 + 1];

    // Issue all 8 loads before any math (independent -> high MLP)
    float4 A[4], Bv[4];
#pragma unroll
    for (int r = 0; r < 4; r++) {
        int row = base_row + r;
        if (row >= M) row = M - 1;  // safe duplicate; discarded below
        const float4* m4 = (const float4*)(mem + (size_t)row * D);
        A[r]  = m4[lane * 2];
        Bv[r] = m4[lane * 2 + 1];
    }

    const float Bf = (float)BQ;
    float acc[4];
#pragma unroll
    for (int r = 0; r < 4; r++) {
        float4 a = A[r], b = Bv[r];
        acc[r] = a.x * (Bf * a.x - 2.f * fa.x)
               + a.y * (Bf * a.y - 2.f * fa.y)
               + a.z * (Bf * a.z - 2.f * fa.z)
               + a.w * (Bf * a.w - 2.f * fa.w)
               + b.x * (Bf * b.x - 2.f * fb.x)
               + b.y * (Bf * b.y - 2.f * fb.y)
               + b.z * (Bf * b.z - 2.f * fb.z)
               + b.w * (Bf * b.w - 2.f * fb.w);
    }
    // Butterfly reductions (all lanes end with totals)
#pragma unroll
    for (int o = 16; o > 0; o >>= 1) {
#pragma unroll
        for (int r = 0; r < 4; r++)
            acc[r] += __shfl_xor_sync(0xffffffffu, acc[r], o);
    }

    if (lane < 4) {
        int row = base_row + lane;
        if (row < M) {
            float v = lane == 0 ? acc[0] : lane == 1 ? acc[1] : lane == 2 ? acc[2] : acc[3];
            // score = -(v + const); ordering depends only on -v
            float score = -v;
            unsigned u = __float_as_uint(score);
            u = (u & 0x80000000u) ? ~u : (u | 0x80000000u);  // monotone map
            unsigned long long key =
                ((unsigned long long)u << 32) | (unsigned)(~row);  // smaller row wins ties
            g_keys[row] = key;
            atomicAdd(&g_hist[u >> 12], 1);
        }
    }
}

// ---------------- K3: chunk sums over 1M bins ----------------
__global__ void k_chunksum() {
    __shared__ int red[256];
    int c = blockIdx.x;       // 1024 chunks of 1024 bins
    int t = threadIdx.x;      // 256 threads, 4 bins each
    const int4* h4 = (const int4*)(g_hist + c * 1024);
    int4 v = h4[t];
    red[t] = v.x + v.y + v.z + v.w;
    __syncthreads();
    for (int st = 128; st > 0; st >>= 1) {
        if (t < st) red[t] += red[t + st];
        __syncthreads();
    }
    if (t == 0) g_chunk[c] = red[0];
}

// ---------------- K4: threshold via two parallel suffix scans ----------------
__global__ void k_thresh() {
    __shared__ int s[NCHUNK];
    __shared__ int sC, sCum;
    int t = threadIdx.x;  // 1024
    s[t] = g_chunk[t];
    __syncthreads();
    // inclusive suffix scan (Hillis-Steele)
    for (int off = 1; off < NCHUNK; off <<= 1) {
        int v = (t + off < NCHUNK) ? s[t + off] : 0;
        __syncthreads();
        s[t] += v;
        __syncthreads();
    }
    if (s[t] >= KTOP && (t == NCHUNK - 1 || s[t + 1] < KTOP)) sC = t;
    __syncthreads();
    int C = sC;
    if (t == 0) sCum = (C == NCHUNK - 1) ? 0 : s[C + 1];  // strictly-above count
    __syncthreads();
    int cumAbove = sCum;
    // refine within chunk C
    s[t] = g_hist[C * 1024 + t];
    __syncthreads();
    for (int off = 1; off < NCHUNK; off <<= 1) {
        int v = (t + off < NCHUNK) ? s[t + off] : 0;
        __syncthreads();
        s[t] += v;
        __syncthreads();
    }
    if (cumAbove + s[t] >= KTOP &&
        (t == NCHUNK - 1 || cumAbove + s[t + 1] < KTOP)) {
        g_Tbin = C * 1024 + t;
    }
}

// ---------------- K5: collect candidates ----------------
__global__ void k_collect(int M) {
    int i = blockIdx.x * blockDim.x + threadIdx.x;
    if (i >= M) return;
    unsigned long long key = g_keys[i];
    int bin = (int)(key >> 44);
    if (bin >= g_Tbin) {
        int p = atomicAdd(&g_ncand, 1);
        if (p < CAND_MAX) g_cand[p] = key;
    }
}

// ---------------- K6: bitonic sort candidates, emit ranked indices ----------------
__global__ void k_sort() {
    __shared__ unsigned long long s[CAND_MAX];  // 32 KB
    int tid = threadIdx.x;  // 1024
    int n = g_ncand;
    if (n > CAND_MAX) n = CAND_MAX;
    for (int i = tid; i < CAND_MAX; i += 1024)
        s[i] = (i < n) ? ~g_cand[i] : ~0ULL;  // ascending on ~key; pads last
    __syncthreads();
    for (int k = 2; k <= CAND_MAX; k <<= 1) {
        for (int j = k >> 1; j > 0; j >>= 1) {
            for (int i = tid; i < CAND_MAX; i += 1024) {
                int ixj = i ^ j;
                if (ixj > i) {
                    unsigned long long va = s[i], vb = s[ixj];
                    bool up = ((i & k) == 0);
                    if ((va > vb) == up) { s[i] = vb; s[ixj] = va; }
                }
            }
            __syncthreads();
        }
    }
    for (int r = tid; r < KTOP; r += 1024) {
        unsigned long long key = ~s[r];
        g_topidx[r] = (int)(~(unsigned)key);
    }
}

// ---------------- K7: gather winning rows ----------------
__global__ void k_gather(const float* __restrict__ mem, float* __restrict__ out) {
    int r = blockIdx.x * 2 + (threadIdx.x >> 6);  // 2 rows per block
    int t = threadIdx.x & 63;
    int idx = g_topidx[r];
    const float4* src = (const float4*)(mem + (size_t)idx * D);
    float4* dst = (float4*)(out + (size_t)r * D);
    dst[t] = src[t];
}

extern "C" void kernel_launch(void* const* d_in, const int* in_sizes, int n_in,
                              void* d_out, int out_size) {
    const float* p0 = (const float*)d_in[0];
    const float* p1 = (const float*)d_in[1];
    const float* feat;
    const float* mem;
    int M;
    if (in_sizes[0] <= in_sizes[1]) { feat = p0; mem = p1; M = in_sizes[1] / D; }
    else                            { feat = p1; mem = p0; M = in_sizes[0] / D; }

    k_zero<<<NBINS / 256, 256>>>();
    k_feat1<<<FEAT_BLOCKS, 256>>>(feat);
    k_feat2<<<1, 256>>>();
    k_scores<<<(M + 31) / 32, 256>>>(mem, M);
    k_chunksum<<<NCHUNK, 256>>>();
    k_thresh<<<1, 1024>>>();
    k_collect<<<(M + 255) / 256, 256>>>(M);
    k_sort<<<1, 1024>>>();
    k_gather<<<KTOP / 2, 128>>>(mem, (float*)d_out);
}